// round 3
// baseline (speedup 1.0000x reference)
#include <cuda_runtime.h>

// Problem constants
#define Bc    32
#define Dc    256
#define HWc   1024
#define Nrows 32768          // B*H*W
#define Kc    2048
#define QN    8388608        // quantized element count (B*D*H*W)
#define IDX_OFF (QN + 2)     // out: [quantized(QN), loss, perplexity, indices(Nrows)]

// Scratch (device globals: no allocation allowed)
__device__ float  g_Et[Kc * Dc];   // transposed codebook (K, D), 2 MB -> L2 resident
__device__ float  g_enorm[Kc];     // ||e_k||^2
__device__ int    g_idx[Nrows];    // argmin indices
__device__ int    g_counts[Kc];    // usage histogram
__device__ double g_sumsq;         // sum (q - x)^2

// ---------------------------------------------------------------------------
// K0: zero per-call accumulators (graph-replay safe)
// ---------------------------------------------------------------------------
__global__ void k_zero() {
    int t = blockIdx.x * blockDim.x + threadIdx.x;
    if (t < Kc) g_counts[t] = 0;
    if (t == 0) g_sumsq = 0.0;
}

// ---------------------------------------------------------------------------
// K1: transpose embedding (D,K) row-major -> Et (K,D) row-major
// ---------------------------------------------------------------------------
__global__ void k_transpose(const float* __restrict__ emb) {
    __shared__ float tile[32][33];
    int k0 = blockIdx.x * 32;
    int d0 = blockIdx.y * 32;
    int tx = threadIdx.x, ty = threadIdx.y;   // block (32, 8)
#pragma unroll
    for (int i = 0; i < 32; i += 8)
        tile[ty + i][tx] = emb[(d0 + ty + i) * Kc + (k0 + tx)];
    __syncthreads();
#pragma unroll
    for (int i = 0; i < 32; i += 8)
        g_Et[(k0 + ty + i) * Dc + (d0 + tx)] = tile[tx][ty + i];
}

// ---------------------------------------------------------------------------
// K1b: per-codeword squared norms (warp per codeword, coalesced on Et rows)
// ---------------------------------------------------------------------------
__global__ void k_norms() {
    int lane = threadIdx.x & 31;
    int warp = threadIdx.x >> 5;
    int k = blockIdx.x * 8 + warp;
    float s = 0.f;
#pragma unroll
    for (int i = 0; i < 8; i++) {
        float v = g_Et[k * Dc + lane + i * 32];
        s += v * v;
    }
#pragma unroll
    for (int o = 16; o; o >>= 1) s += __shfl_xor_sync(0xffffffffu, s, o);
    if (lane == 0) g_enorm[k] = s;
}

// ---------------------------------------------------------------------------
// K2: fused GEMM + argmin.
//   CTA tile: 128 rows x 64 codewords, loop over all 32 codeword tiles.
//   Threads 256 = (tx:16 col-groups x 4) x (ty:16 row-groups x 8).
//   D reduced in chunks of 32 through shared memory.
//   dist = ||e||^2 - 2 * x.e  (row-constant ||x||^2 dropped)
// ---------------------------------------------------------------------------
__global__ void __launch_bounds__(256) k_argmin(const float* __restrict__ in,
                                                float* __restrict__ out) {
    __shared__ __align__(16) float Xs[32][128];   // [d-chunk][row]
    __shared__ __align__(16) float Es[32][68];    // [d-chunk][col] (padded)
    __shared__ float ens[64];
    __shared__ float red_val[128 * 16];
    __shared__ int   red_idx[128 * 16];

    const int tid = threadIdx.x;
    const int tx = tid & 15;       // col group
    const int ty = tid >> 4;       // row group
    const int m0 = blockIdx.x * 128;
    const int b  = m0 >> 10;       // 128-row tile stays inside one image (1024 rows/image)
    const int p0 = m0 & 1023;
    const float* inb = in + (size_t)b * (Dc * HWc);

    float best_val[8];
    int   best_idx[8];
#pragma unroll
    for (int i = 0; i < 8; i++) { best_val[i] = 3.4e38f; best_idx[i] = 0; }

    for (int nt = 0; nt < Kc / 64; nt++) {
        float acc[8][4];
#pragma unroll
        for (int i = 0; i < 8; i++)
#pragma unroll
            for (int j = 0; j < 4; j++) acc[i][j] = 0.f;

        if (tid < 64) ens[tid] = g_enorm[nt * 64 + tid];

        for (int kc = 0; kc < Dc; kc += 32) {
            // load X chunk: 128 rows x 32 d's (coalesced over rows), clamp here
#pragma unroll
            for (int i = 0; i < 16; i++) {
                int ii = tid + i * 256;
                int dd = ii >> 7, r = ii & 127;
                float v = inb[(kc + dd) * HWc + p0 + r];
                Xs[dd][r] = fminf(fmaxf(v, -10.f), 10.f);
            }
            // load E chunk: 64 codewords x 32 d's (coalesced over d)
#pragma unroll
            for (int i = 0; i < 8; i++) {
                int ii = tid + i * 256;
                int dd = ii & 31, c = ii >> 5;
                Es[dd][c] = g_Et[(nt * 64 + c) * Dc + (kc + dd)];
            }
            __syncthreads();

#pragma unroll
            for (int dd = 0; dd < 32; dd++) {
                const float4 xa = *(const float4*)(&Xs[dd][ty * 8]);
                const float4 xb = *(const float4*)(&Xs[dd][ty * 8 + 4]);
                const float4 ev = *(const float4*)(&Es[dd][tx * 4]);
                float xv[8] = {xa.x, xa.y, xa.z, xa.w, xb.x, xb.y, xb.z, xb.w};
#pragma unroll
                for (int i = 0; i < 8; i++) {
                    acc[i][0] += xv[i] * ev.x;
                    acc[i][1] += xv[i] * ev.y;
                    acc[i][2] += xv[i] * ev.z;
                    acc[i][3] += xv[i] * ev.w;
                }
            }
            __syncthreads();
        }

        // distances for this codeword tile; update running argmin
#pragma unroll
        for (int i = 0; i < 8; i++)
#pragma unroll
            for (int j = 0; j < 4; j++) {
                float d = ens[tx * 4 + j] - 2.f * acc[i][j];
                if (d < best_val[i]) {
                    best_val[i] = d;
                    best_idx[i] = nt * 64 + tx * 4 + j;
                }
            }
        __syncthreads();   // protect ens before next tile overwrites it
    }

    // cross-thread (over tx) argmin reduction per row
#pragma unroll
    for (int i = 0; i < 8; i++) {
        red_val[(ty * 8 + i) * 16 + tx] = best_val[i];
        red_idx[(ty * 8 + i) * 16 + tx] = best_idx[i];
    }
    __syncthreads();

    if (tid < 128) {
        float bv = 3.4e38f;
        int bk = 0;
#pragma unroll
        for (int t = 0; t < 16; t++) {
            float v = red_val[tid * 16 + t];
            if (v < bv) { bv = v; bk = red_idx[tid * 16 + t]; }
        }
        int grow = m0 + tid;
        g_idx[grow] = bk;
        out[IDX_OFF + grow] = (float)bk;
        atomicAdd(&g_counts[bk], 1);
    }
}

// ---------------------------------------------------------------------------
// K3: gather quantized into output + accumulate sum((q - x)^2)
//   quantized_st == quantized numerically (straight-through).
// ---------------------------------------------------------------------------
__global__ void __launch_bounds__(256) k_gather(const float* __restrict__ in,
                                                float* __restrict__ out) {
    int t = blockIdx.x * 256 + threadIdx.x;   // linear index into (B,D,H,W)
    int p  = t & 1023;
    int bd = t >> 10;
    int d  = bd & 255;
    int b  = bd >> 8;
    int k  = g_idx[(b << 10) | p];
    float q = g_Et[k * Dc + d];
    float x = in[t];
    out[t] = q;
    float diff = q - x;
    float s = diff * diff;
#pragma unroll
    for (int o = 16; o; o >>= 1) s += __shfl_xor_sync(0xffffffffu, s, o);
    __shared__ float ws[8];
    int lane = threadIdx.x & 31, w = threadIdx.x >> 5;
    if (lane == 0) ws[w] = s;
    __syncthreads();
    if (threadIdx.x == 0) {
        float bs = ws[0] + ws[1] + ws[2] + ws[3] + ws[4] + ws[5] + ws[6] + ws[7];
        atomicAdd(&g_sumsq, (double)bs);
    }
}

// ---------------------------------------------------------------------------
// K4: finalize loss + perplexity
//   loss = q_latent + 0.25*e_latent = 1.25 * mean((q - x)^2)
// ---------------------------------------------------------------------------
__global__ void k_final(float* __restrict__ out) {
    __shared__ double sh[256];
    int t = threadIdx.x;
    double local = 0.0;
    for (int k = t; k < Kc; k += 256) {
        double pr = (double)g_counts[k] / (double)Nrows;
        local += pr * log(pr + 1e-10);
    }
    sh[t] = local;
    __syncthreads();
    for (int o = 128; o; o >>= 1) {
        if (t < o) sh[t] += sh[t + o];
        __syncthreads();
    }
    if (t == 0) {
        out[QN]     = (float)(1.25 * g_sumsq / (double)QN);
        out[QN + 1] = (float)exp(-sh[0]);
    }
}

// ---------------------------------------------------------------------------
extern "C" void kernel_launch(void* const* d_in, const int* in_sizes, int n_in,
                              void* d_out, int out_size) {
    const float* in  = (const float*)d_in[0];
    const float* emb = (const float*)d_in[1];
    if (n_in >= 2 && in_sizes[0] == Dc * Kc) {  // defensive: inputs swapped?
        in  = (const float*)d_in[1];
        emb = (const float*)d_in[0];
    }
    float* out = (float*)d_out;

    k_zero<<<8, 256>>>();
    k_transpose<<<dim3(Kc / 32, Dc / 32), dim3(32, 8)>>>(emb);
    k_norms<<<Kc / 8, 256>>>();
    k_argmin<<<Nrows / 128, 256>>>(in, out);
    k_gather<<<QN / 256, 256>>>(in, out);
    k_final<<<1, 256>>>(out);
}

// round 6
// speedup vs baseline: 1.4051x; 1.4051x over previous
#include <cuda_runtime.h>
#include <cuda_bf16.h>
#include <cstdint>

// Problem constants
#define Bc    32
#define Dc    256
#define HWc   1024
#define Nrows 32768          // B*H*W
#define Kc    2048
#define QN    8388608        // quantized element count (B*D*H*W)
#define IDX_OFF (QN + 2)     // out: [quantized(QN), loss, perplexity, indices(Nrows)]

// Scratch (device globals: no allocation allowed)
__device__ float          g_Et[Kc * Dc];        // transposed codebook (K, D) fp32
__device__ float          g_enorm[Kc];          // ||e_k||^2
__device__ __nv_bfloat16  g_Ehl[Kc * 512];      // per codeword: [Eh(256) | El(256)]
__device__ __nv_bfloat16  g_Xhl[Nrows * 512];   // per row:      [Xh(256) | Xl(256)] (clamped)
__device__ int            g_idx[Nrows];         // argmin indices
__device__ int            g_counts[Kc];         // usage histogram
__device__ int            g_nfb;                // fallback row count
__device__ int            g_fb[Nrows];          // fallback row list
__device__ double         g_sumsq;              // sum (q - x)^2

// ---------------------------------------------------------------------------
// helpers
// ---------------------------------------------------------------------------
__device__ __forceinline__ uint32_t smem_u32(const void* p) {
    uint32_t a;
    asm("{ .reg .u64 t; cvta.to.shared.u64 t, %1; cvt.u32.u64 %0, t; }"
        : "=r"(a) : "l"(p));
    return a;
}

#define STS128(addr, v) \
    asm volatile("st.shared.v4.b32 [%0], {%1, %2, %3, %4};" \
                 :: "r"(addr), "r"((v).x), "r"((v).y), "r"((v).z), "r"((v).w) : "memory")

#define CPASYNC16(dst, src) \
    asm volatile("cp.async.cg.shared.global [%0], [%1], 16;" \
                 :: "r"(dst), "l"(src) : "memory")
#define CPASYNC_COMMIT() asm volatile("cp.async.commit_group;" ::: "memory")
#define CPASYNC_WAIT1()  asm volatile("cp.async.wait_group 1;" ::: "memory")

#define LDSM4(r0, r1, r2, r3, addr) \
    asm volatile("ldmatrix.sync.aligned.m8n8.x4.shared.b16 {%0,%1,%2,%3}, [%4];" \
                 : "=r"(r0), "=r"(r1), "=r"(r2), "=r"(r3) : "r"(addr))

#define MMA16816(d, a, b0, b1) \
    asm volatile("mma.sync.aligned.m16n8k16.row.col.f32.bf16.bf16.f32 " \
                 "{%0,%1,%2,%3}, {%4,%5,%6,%7}, {%8,%9}, {%0,%1,%2,%3};" \
                 : "+f"((d)[0]), "+f"((d)[1]), "+f"((d)[2]), "+f"((d)[3]) \
                 : "r"((a)[0]), "r"((a)[1]), "r"((a)[2]), "r"((a)[3]), \
                   "r"(b0), "r"(b1))

// ---------------------------------------------------------------------------
// K0: zero per-call accumulators (graph-replay safe)
// ---------------------------------------------------------------------------
__global__ void k_zero() {
    int t = blockIdx.x * blockDim.x + threadIdx.x;
    if (t < Kc) g_counts[t] = 0;
    if (t == 0) { g_sumsq = 0.0; g_nfb = 0; }
}

// ---------------------------------------------------------------------------
// K1: transpose embedding (D,K) -> Et (K,D) fp32
// ---------------------------------------------------------------------------
__global__ void k_transpose(const float* __restrict__ emb) {
    __shared__ float tile[32][33];
    int k0 = blockIdx.x * 32;
    int d0 = blockIdx.y * 32;
    int tx = threadIdx.x, ty = threadIdx.y;   // block (32, 8)
#pragma unroll
    for (int i = 0; i < 32; i += 8)
        tile[ty + i][tx] = emb[(d0 + ty + i) * Kc + (k0 + tx)];
    __syncthreads();
#pragma unroll
    for (int i = 0; i < 32; i += 8)
        g_Et[(k0 + ty + i) * Dc + (d0 + tx)] = tile[tx][ty + i];
}

// ---------------------------------------------------------------------------
// K1b: per-codeword squared norms
// ---------------------------------------------------------------------------
__global__ void k_norms() {
    int lane = threadIdx.x & 31;
    int warp = threadIdx.x >> 5;
    int k = blockIdx.x * 8 + warp;
    float s = 0.f;
#pragma unroll
    for (int i = 0; i < 8; i++) {
        float v = g_Et[k * Dc + lane + i * 32];
        s += v * v;
    }
#pragma unroll
    for (int o = 16; o; o >>= 1) s += __shfl_xor_sync(0xffffffffu, s, o);
    if (lane == 0) g_enorm[k] = s;
}

// ---------------------------------------------------------------------------
// K1c: codebook fp32 -> bf16 hi/lo  [Eh | El] per row
// ---------------------------------------------------------------------------
__global__ void k_ebf16() {
    int t = blockIdx.x * 256 + threadIdx.x;   // t over Kc*Dc
    int k = t >> 8, d = t & 255;
    float v = g_Et[t];
    __nv_bfloat16 h = __float2bfloat16(v);
    g_Ehl[k * 512 + d]       = h;
    g_Ehl[k * 512 + 256 + d] = __float2bfloat16(v - __bfloat162float(h));
}

// ---------------------------------------------------------------------------
// K1d: inputs (B,D,H,W) -> clamped (N, [Xh|Xl]) bf16 (transpose through smem)
// ---------------------------------------------------------------------------
__global__ void k_prep_x(const float* __restrict__ in) {
    __shared__ float tile[32][33];
    int p0 = blockIdx.x * 32, d0 = blockIdx.y * 32, b = blockIdx.z;
    int tx = threadIdx.x, ty = threadIdx.y;   // block (32, 8)
    const float* ib = in + (size_t)b * (Dc * HWc);
#pragma unroll
    for (int i = 0; i < 32; i += 8)
        tile[ty + i][tx] = ib[(d0 + ty + i) * HWc + p0 + tx];
    __syncthreads();
#pragma unroll
    for (int i = 0; i < 32; i += 8) {
        float v = tile[tx][ty + i];
        v = fminf(fmaxf(v, -10.f), 10.f);
        __nv_bfloat16 h = __float2bfloat16(v);
        int row = b * HWc + p0 + ty + i;
        g_Xhl[row * 512 + d0 + tx]       = h;
        g_Xhl[row * 512 + 256 + d0 + tx] = __float2bfloat16(v - __bfloat162float(h));
    }
}

// ---------------------------------------------------------------------------
// K2: mma.sync bf16 distance GEMM + fused argmin.
//   dot = Ah.Bh + Ah.Bl + Al.Bh (augmented K' = 768, 12 chunks of 64 per
//   128-codeword tile; chunk c: region r=c/4 selects A half / B half).
//   CTA: 128 rows x all 2048 codewords. A tile resident in swizzled smem,
//   B double-buffered 16KB chunks via cp.async. 8 warps = 4(M) x 2(N),
//   warp tile 32x64, m16n8k16.
// ---------------------------------------------------------------------------
#define OFF_B   131072
#define OFF_EN  163840
#define OFF_RED 172032
#define SMEM_TOTAL 184320
#define NCHUNKS 192            // 16 N-tiles * 12 chunks
#define MARGIN_TH 0.01f

__device__ __forceinline__ void issue_chunk(int g, uint32_t smB, int tid) {
    if (g < NCHUNKS) {
        const int nt = g / 12, c = g % 12;
        const int r = c >> 2, kk = (c & 3) * 64;
        const int khalf = (r == 1);
        const uint4* Bg = (const uint4*)g_Ehl;
        const uint32_t buf = smB + (uint32_t)(g & 1) * 16384u;
#pragma unroll
        for (int i = 0; i < 4; i++) {
            int u = tid + i * 256;
            int row = u >> 3, c16 = u & 7;
            const uint4* src = Bg + (((nt * 128 + row) << 6) + khalf * 32 + (kk >> 3) + c16);
            uint32_t dst = buf + (uint32_t)(row * 128 + ((c16 ^ (row & 7)) << 4));
            CPASYNC16(dst, src);
        }
    }
    CPASYNC_COMMIT();
}

__global__ void __launch_bounds__(256, 1) k_argmin_mma() {
    extern __shared__ __align__(1024) char sm[];
    const uint32_t smb = smem_u32(sm);
    const uint32_t smA = smb;
    const uint32_t smB = smb + OFF_B;
    float* s_en = (float*)(sm + OFF_EN);
    float* rv  = (float*)(sm + OFF_RED);
    float* rv2 = rv + 1024;
    int*   ri  = (int*)(rv2 + 1024);

    const int tid  = threadIdx.x;
    const int lane = tid & 31;
    const int wid  = tid >> 5;
    const int wm = wid & 3;          // M group (0..3)
    const int wn = wid >> 2;         // N group (0..1)
    const int gid = lane >> 2;
    const int tid4 = lane & 3;
    const int m0 = blockIdx.x * 128;

    // ---- load A tile [128 x 512] bf16, swizzled ----
    {
        const uint4* Xg = (const uint4*)g_Xhl;   // 64 16B-units per row
#pragma unroll
        for (int i = 0; i < 32; i++) {
            int u = tid + i * 256;
            int row = u >> 6, c16 = u & 63;
            uint4 v = Xg[(size_t)(m0 + row) * 64 + c16];
            uint32_t dst = smA + (uint32_t)(row * 1024 + ((c16 ^ (row & 7)) << 4));
            STS128(dst, v);
        }
#pragma unroll
        for (int i = 0; i < 8; i++) s_en[tid + i * 256] = g_enorm[tid + i * 256];
    }
    __syncthreads();

    float acc[2][8][4];
#pragma unroll
    for (int i = 0; i < 2; i++)
#pragma unroll
        for (int j = 0; j < 8; j++)
#pragma unroll
            for (int c = 0; c < 4; c++) acc[i][j][c] = 0.f;

    float best[4], best2[4];
    int bidx[4];
#pragma unroll
    for (int s = 0; s < 4; s++) { best[s] = 3.4e38f; best2[s] = 3.4e38f; bidx[s] = 0; }

    issue_chunk(0, smB, tid);
    issue_chunk(1, smB, tid);

    for (int g = 0; g < NCHUNKS; g++) {
        CPASYNC_WAIT1();
        __syncthreads();

        const int nt = g / 12, c = g % 12;
        const int r = c >> 2, kk = (c & 3) * 64;
        const int half = (r == 2);
        const uint32_t bufB = smB + (uint32_t)(g & 1) * 16384u;

#pragma unroll
        for (int s = 0; s < 4; s++) {
            uint32_t a[2][4];
#pragma unroll
            for (int i = 0; i < 2; i++) {
                int row = wm * 32 + i * 16 + (lane & 15);
                int c16 = half * 32 + (kk >> 3) + s * 2 + (lane >> 4);
                uint32_t addr = smA + (uint32_t)(row * 1024 + ((c16 ^ (row & 7)) << 4));
                LDSM4(a[i][0], a[i][1], a[i][2], a[i][3], addr);
            }
#pragma unroll
            for (int j16 = 0; j16 < 4; j16++) {
                uint32_t b0, b1, b2, b3;
                int row = wn * 64 + j16 * 16 + (lane & 7) + ((lane & 16) ? 8 : 0);
                int c16 = s * 2 + ((lane >> 3) & 1);
                uint32_t addr = bufB + (uint32_t)(row * 128 + ((c16 ^ (row & 7)) << 4));
                LDSM4(b0, b1, b2, b3, addr);
                MMA16816(acc[0][j16 * 2],     a[0], b0, b1);
                MMA16816(acc[0][j16 * 2 + 1], a[0], b2, b3);
                MMA16816(acc[1][j16 * 2],     a[1], b0, b1);
                MMA16816(acc[1][j16 * 2 + 1], a[1], b2, b3);
            }
        }

        if (c == 11) {
            // epilogue: distances + running argmin for this 128-codeword tile
#pragma unroll
            for (int i = 0; i < 2; i++)
#pragma unroll
                for (int j = 0; j < 8; j++)
#pragma unroll
                    for (int cc = 0; cc < 4; cc++) {
                        int n = nt * 128 + wn * 64 + j * 8 + tid4 * 2 + (cc & 1);
                        float d = s_en[n] - 2.f * acc[i][j][cc];
                        int sl = i * 2 + (cc >> 1);
                        if (d < best[sl]) {
                            best2[sl] = best[sl]; best[sl] = d; bidx[sl] = n;
                        } else if (d < best2[sl]) {
                            best2[sl] = d;
                        }
                        acc[i][j][cc] = 0.f;
                    }
        }
        __syncthreads();
        issue_chunk(g + 2, smB, tid);
    }

    // ---- cross-warp argmin reduction (8 candidates per row) ----
#pragma unroll
    for (int sl = 0; sl < 4; sl++) {
        int i = sl >> 1, h = sl & 1;
        int row = wm * 32 + i * 16 + gid + 8 * h;
        int s8 = wn * 4 + tid4;
        rv[row * 8 + s8]  = best[sl];
        rv2[row * 8 + s8] = best2[sl];
        ri[row * 8 + s8]  = bidx[sl];
    }
    __syncthreads();

    if (tid < 128) {
        float b1 = rv[tid * 8], b2 = rv2[tid * 8];
        int bi = ri[tid * 8];
#pragma unroll
        for (int s = 1; s < 8; s++) {
            float v = rv[tid * 8 + s], v2 = rv2[tid * 8 + s];
            int idx = ri[tid * 8 + s];
            if (v < b1 || (v == b1 && idx < bi)) {
                b2 = fminf(b1, v2);
                b1 = v; bi = idx;
            } else {
                b2 = fminf(b2, v);
            }
        }
        g_idx[m0 + tid] = bi;
        if (b2 - b1 < MARGIN_TH) {
            int p = atomicAdd(&g_nfb, 1);
            g_fb[p] = m0 + tid;
        }
    }
}

// ---------------------------------------------------------------------------
// K2b: exact fp32 re-solve for small-margin rows
// ---------------------------------------------------------------------------
__global__ void __launch_bounds__(256) k_fallback() {
    __shared__ float xr[256];
    __shared__ float bv[256];
    __shared__ int   bi[256];
    const int n = g_nfb;
    for (int i = blockIdx.x; i < n; i += gridDim.x) {
        const int row = g_fb[i];
        __syncthreads();
        xr[threadIdx.x] = __bfloat162float(g_Xhl[row * 512 + threadIdx.x])
                        + __bfloat162float(g_Xhl[row * 512 + 256 + threadIdx.x]);
        __syncthreads();
        float best = 3.4e38f;
        int bidx = Kc;
        for (int k8 = 0; k8 < 8; k8++) {
            const int k = k8 * 256 + threadIdx.x;
            const float* e = g_Et + k * 256;
            float dot = 0.f;
#pragma unroll 8
            for (int d = 0; d < 256; d++) dot += xr[d] * e[d];
            float dist = g_enorm[k] - 2.f * dot;
            if (dist < best || (dist == best && k < bidx)) { best = dist; bidx = k; }
        }
        bv[threadIdx.x] = best;
        bi[threadIdx.x] = bidx;
        __syncthreads();
        for (int o = 128; o; o >>= 1) {
            if (threadIdx.x < o) {
                float ov = bv[threadIdx.x + o];
                int   oi = bi[threadIdx.x + o];
                if (ov < bv[threadIdx.x] ||
                    (ov == bv[threadIdx.x] && oi < bi[threadIdx.x])) {
                    bv[threadIdx.x] = ov;
                    bi[threadIdx.x] = oi;
                }
            }
            __syncthreads();
        }
        if (threadIdx.x == 0) g_idx[row] = bi[0];
        __syncthreads();
    }
}

// ---------------------------------------------------------------------------
// K2c: histogram + index output (after fallback fixes)
// ---------------------------------------------------------------------------
__global__ void k_hist(float* __restrict__ out) {
    const int m = blockIdx.x * 256 + threadIdx.x;
    const int k = g_idx[m];
    out[IDX_OFF + m] = (float)k;
    atomicAdd(&g_counts[k], 1);
}

// ---------------------------------------------------------------------------
// K3: gather quantized into output + accumulate sum((q - x)^2)
// ---------------------------------------------------------------------------
__global__ void __launch_bounds__(256) k_gather(const float* __restrict__ in,
                                                float* __restrict__ out) {
    int t = blockIdx.x * 256 + threadIdx.x;
    int p  = t & 1023;
    int bd = t >> 10;
    int d  = bd & 255;
    int b  = bd >> 8;
    int k  = g_idx[(b << 10) | p];
    float q = g_Et[k * Dc + d];
    float x = in[t];
    out[t] = q;
    float diff = q - x;
    float s = diff * diff;
#pragma unroll
    for (int o = 16; o; o >>= 1) s += __shfl_xor_sync(0xffffffffu, s, o);
    __shared__ float ws[8];
    int lane = threadIdx.x & 31, w = threadIdx.x >> 5;
    if (lane == 0) ws[w] = s;
    __syncthreads();
    if (threadIdx.x == 0) {
        float bs = ws[0] + ws[1] + ws[2] + ws[3] + ws[4] + ws[5] + ws[6] + ws[7];
        atomicAdd(&g_sumsq, (double)bs);
    }
}

// ---------------------------------------------------------------------------
// K4: finalize loss + perplexity
// ---------------------------------------------------------------------------
__global__ void k_final(float* __restrict__ out) {
    __shared__ double sh[256];
    int t = threadIdx.x;
    double local = 0.0;
    for (int k = t; k < Kc; k += 256) {
        double pr = (double)g_counts[k] / (double)Nrows;
        local += pr * log(pr + 1e-10);
    }
    sh[t] = local;
    __syncthreads();
    for (int o = 128; o; o >>= 1) {
        if (t < o) sh[t] += sh[t + o];
        __syncthreads();
    }
    if (t == 0) {
        out[QN]     = (float)(1.25 * g_sumsq / (double)QN);
        out[QN + 1] = (float)exp(-sh[0]);
    }
}

// ---------------------------------------------------------------------------
extern "C" void kernel_launch(void* const* d_in, const int* in_sizes, int n_in,
                              void* d_out, int out_size) {
    const float* in  = (const float*)d_in[0];
    const float* emb = (const float*)d_in[1];
    if (n_in >= 2 && in_sizes[0] == Dc * Kc) {  // defensive: inputs swapped?
        in  = (const float*)d_in[1];
        emb = (const float*)d_in[0];
    }
    float* out = (float*)d_out;

    cudaFuncSetAttribute(k_argmin_mma, cudaFuncAttributeMaxDynamicSharedMemorySize,
                         SMEM_TOTAL);

    k_zero<<<8, 256>>>();
    k_transpose<<<dim3(Kc / 32, Dc / 32), dim3(32, 8)>>>(emb);
    k_norms<<<Kc / 8, 256>>>();
    k_ebf16<<<(Kc * Dc) / 256, 256>>>();
    k_prep_x<<<dim3(HWc / 32, Dc / 32, Bc), dim3(32, 8)>>>(in);
    k_argmin_mma<<<Nrows / 128, 256, SMEM_TOTAL>>>();
    k_fallback<<<148, 256>>>();
    k_hist<<<Nrows / 256, 256>>>(out);
    k_gather<<<QN / 256, 256>>>(in, out);
    k_final<<<1, 256>>>(out);
}